// round 16
// baseline (speedup 1.0000x reference)
#include <cuda_runtime.h>
#include <cuda_fp16.h>
#include <math.h>
#include <cstdint>

// Problem constants
#define BB   2
#define SS   2048
#define DD   768
#define HH   12
#define HDD  64
#define MM   (BB * SS)        // 4096
#define NQKV (3 * DD)         // 2304

typedef __half h16;

// Scratch (__device__ globals; no allocation allowed)
__device__ h16 g_qkvh[MM * NQKV];
__device__ h16 g_qkvl[MM * NQKV];
__device__ h16 g_attnh[MM * DD];
__device__ h16 g_attnl[MM * DD];
__device__ h16 g_Xh[MM * DD];
__device__ h16 g_Xl[MM * DD];
__device__ h16 g_Bqh[NQKV * DD];
__device__ h16 g_Bql[NQKV * DD];
__device__ h16 g_Boh[DD * DD];
__device__ h16 g_Bol[DD * DD];

// ---------------------------------------------------------------------------
// Helpers
// ---------------------------------------------------------------------------
__device__ __forceinline__ uint32_t smem_u32(const void* p) {
    uint32_t a;
    asm("{ .reg .u64 t; cvta.to.shared.u64 t, %1; cvt.u32.u64 %0, t; }" : "=r"(a) : "l"(p));
    return a;
}

__device__ __forceinline__ float ex2f(float x) {
    float r;
    asm("ex2.approx.ftz.f32 %0, %1;" : "=f"(r) : "f"(x));
    return r;
}

// pack two floats into fp16x2 (x0 -> lower 16 bits)
__device__ __forceinline__ uint32_t packh(float x0, float x1) {
    __half2 h = __floats2half2_rn(x0, x1);
    return *(uint32_t*)&h;
}

// fp16 hi/lo split of a float pair (hi = rn(x), lo = rn(x - hi))
__device__ __forceinline__ void packsplit(float x0, float x1, uint32_t& hi, uint32_t& lo) {
    __half2 h = __floats2half2_rn(x0, x1);
    hi = *(uint32_t*)&h;
    float2 f = __half22float2(h);
    __half2 l = __floats2half2_rn(x0 - f.x, x1 - f.y);
    lo = *(uint32_t*)&l;
}

__device__ __forceinline__ void mma16816(float* c,
                                         uint32_t a0, uint32_t a1, uint32_t a2, uint32_t a3,
                                         uint32_t b0, uint32_t b1) {
    asm volatile(
        "mma.sync.aligned.m16n8k16.row.col.f32.f16.f16.f32 "
        "{%0,%1,%2,%3}, {%4,%5,%6,%7}, {%8,%9}, {%0,%1,%2,%3};\n"
        : "+f"(c[0]), "+f"(c[1]), "+f"(c[2]), "+f"(c[3])
        : "r"(a0), "r"(a1), "r"(a2), "r"(a3), "r"(b0), "r"(b1));
}

__device__ __forceinline__ void ldsm4t(uint32_t* r, uint32_t saddr) {
    asm volatile("ldmatrix.sync.aligned.m8n8.x4.trans.shared.b16 {%0,%1,%2,%3}, [%4];"
                 : "=r"(r[0]), "=r"(r[1]), "=r"(r[2]), "=r"(r[3]) : "r"(saddr));
}

__device__ __forceinline__ void cp16(uint32_t dst, const void* src) {
    asm volatile("cp.async.cg.shared.global [%0], [%1], 16;" :: "r"(dst), "l"(src));
}
#define CP_COMMIT() asm volatile("cp.async.commit_group;" ::: "memory")
#define CP_WAIT0()  asm volatile("cp.async.wait_group 0;" ::: "memory")
#define CP_WAIT1()  asm volatile("cp.async.wait_group 1;" ::: "memory")

// ---------------------------------------------------------------------------
// Prep kernels
// ---------------------------------------------------------------------------
__global__ void split_pair_kernel(const float* __restrict__ x,
                                  h16* __restrict__ h, h16* __restrict__ l, int n4)
{
    int i = blockIdx.x * blockDim.x + threadIdx.x;
    if (i < n4) {
        float4 v = ((const float4*)x)[i];
        uint32_t h01, l01, h23, l23;
        packsplit(v.x, v.y, h01, l01);
        packsplit(v.z, v.w, h23, l23);
        ((uint2*)h)[i] = make_uint2(h01, h23);
        ((uint2*)l)[i] = make_uint2(l01, l23);
    }
}

__global__ void transpose_split_kernel(const float* __restrict__ W,
                                       h16* __restrict__ Th, h16* __restrict__ Tl,
                                       int Kd, int Nd)
{
    __shared__ float tile[32][33];
    int n0 = blockIdx.x * 32, k0 = blockIdx.y * 32;
    int tx = threadIdx.x, ty = threadIdx.y;   // (32, 8)
    #pragma unroll
    for (int i = 0; i < 4; i++)
        tile[ty + i * 8][tx] = W[(size_t)(k0 + ty + i * 8) * Nd + n0 + tx];
    __syncthreads();
    int idx = ty * 32 + tx;
    int n = idx >> 3, kp = idx & 7;
    #pragma unroll
    for (int w = 0; w < 2; w++) {
        int k2 = (kp + w * 8) * 2;
        uint32_t hh, ll;
        packsplit(tile[k2][n], tile[k2 + 1][n], hh, ll);
        *(uint32_t*)(Th + (size_t)(n0 + n) * Kd + k0 + k2) = hh;
        *(uint32_t*)(Tl + (size_t)(n0 + n) * Kd + k0 + k2) = ll;
    }
}

// ---------------------------------------------------------------------------
// GEMM (fp16 compensated): C[M,N] = A[M,K] @ Bt[N,K]^T + bias
// R7-proven pipeline: 128x128 block, K-chunk 32, double buffer, scalar LDS
// fragment loads (stride 40, bank-clean), 2 syncs/chunk, 2 CTAs/SM.
// PASSES = 3: hh + hl + lh; PASSES = 2: hh + lh; PASSES = 1: hh only.
// ---------------------------------------------------------------------------
#define ASTR 40
#define TILEE (128 * ASTR)
#define ABYTES (TILEE * 2)

template<bool SPLIT_OUT, int PASSES>
__global__ __launch_bounds__(256, 2) void gemm_h16_kernel(
    const h16* __restrict__ Ah_g, const h16* __restrict__ Al_g,
    const h16* __restrict__ Bh_g, const h16* __restrict__ Bl_g,
    const float* __restrict__ bias,
    float* __restrict__ C, h16* __restrict__ Ch, h16* __restrict__ Cl,
    int M, int N, int K)
{
    extern __shared__ h16 smb[];
    const uint32_t sm0 = smem_u32(smb);

    const int tid = threadIdx.x;
    const int lane = tid & 31, warp = tid >> 5;
    const int g = lane >> 2, t = lane & 3;
    const int m0 = blockIdx.y * 128, n0 = blockIdx.x * 128;
    const int wm = (warp >> 2) * 64, wn = (warp & 3) * 32;

    float acc[4][4][4];
    #pragma unroll
    for (int mt = 0; mt < 4; mt++)
        #pragma unroll
        for (int nt = 0; nt < 4; nt++)
            #pragma unroll
            for (int r = 0; r < 4; r++) acc[mt][nt][r] = 0.f;

    const int NCH = K / 32;

    auto stage = [&](int ch) {
        const int kb = ch * 32;
        const uint32_t bb = sm0 + (ch & 1) * 4 * ABYTES;
        #pragma unroll
        for (int i = 0; i < 2; i++) {
            int idx = tid + i * 256;
            int r = idx >> 2, cc = idx & 3;
            uint32_t doff = r * 80 + cc * 16;
            cp16(bb + doff,              Ah_g + (size_t)(m0 + r) * K + kb + cc * 8);
            if (PASSES >= 2)
                cp16(bb + ABYTES + doff, Al_g + (size_t)(m0 + r) * K + kb + cc * 8);
            cp16(bb + 2 * ABYTES + doff, Bh_g + (size_t)(n0 + r) * K + kb + cc * 8);
            if (PASSES == 3)
                cp16(bb + 3 * ABYTES + doff, Bl_g + (size_t)(n0 + r) * K + kb + cc * 8);
        }
        CP_COMMIT();
    };

    stage(0);
    stage(1);

    for (int c = 0; c < NCH; c++) {
        if (c == NCH - 1) { CP_WAIT0(); } else { CP_WAIT1(); }
        __syncthreads();

        const h16* bA_h = smb + (size_t)(c & 1) * 4 * TILEE;
        const h16* bA_l = bA_h + TILEE;
        const h16* bB_h = bA_h + 2 * TILEE;
        const h16* bB_l = bA_h + 3 * TILEE;

        #pragma unroll
        for (int st = 0; st < 2; st++) {
            const int k0 = st * 16;
            uint32_t bh[4][2], bl[4][2];
            #pragma unroll
            for (int nt = 0; nt < 4; nt++) {
                const h16* kr = bB_h + (wn + nt * 8 + g) * ASTR + k0 + 2 * t;
                bh[nt][0] = *(const uint32_t*)kr;
                bh[nt][1] = *(const uint32_t*)(kr + 8);
                if (PASSES == 3) {
                    const h16* kl = bB_l + (wn + nt * 8 + g) * ASTR + k0 + 2 * t;
                    bl[nt][0] = *(const uint32_t*)kl;
                    bl[nt][1] = *(const uint32_t*)(kl + 8);
                }
            }
            #pragma unroll
            for (int mt = 0; mt < 4; mt++) {
                const h16* ar = bA_h + (wm + mt * 16 + g) * ASTR + k0 + 2 * t;
                uint32_t ah0 = *(const uint32_t*)ar;
                uint32_t ah1 = *(const uint32_t*)(ar + 8 * ASTR);
                uint32_t ah2 = *(const uint32_t*)(ar + 8);
                uint32_t ah3 = *(const uint32_t*)(ar + 8 * ASTR + 8);
                uint32_t al0 = 0, al1 = 0, al2 = 0, al3 = 0;
                if (PASSES >= 2) {
                    const h16* al = bA_l + (wm + mt * 16 + g) * ASTR + k0 + 2 * t;
                    al0 = *(const uint32_t*)al;
                    al1 = *(const uint32_t*)(al + 8 * ASTR);
                    al2 = *(const uint32_t*)(al + 8);
                    al3 = *(const uint32_t*)(al + 8 * ASTR + 8);
                }
                #pragma unroll
                for (int nt = 0; nt < 4; nt++) {
                    mma16816(acc[mt][nt], ah0, ah1, ah2, ah3, bh[nt][0], bh[nt][1]);
                    if (PASSES == 3)
                        mma16816(acc[mt][nt], ah0, ah1, ah2, ah3, bl[nt][0], bl[nt][1]);
                    if (PASSES >= 2)
                        mma16816(acc[mt][nt], al0, al1, al2, al3, bh[nt][0], bh[nt][1]);
                }
            }
        }
        __syncthreads();
        if (c + 2 < NCH) stage(c + 2);
    }

    #pragma unroll
    for (int mt = 0; mt < 4; mt++) {
        int r0 = m0 + wm + mt * 16 + g;
        #pragma unroll
        for (int nt = 0; nt < 4; nt++) {
            int cc = n0 + wn + nt * 8 + 2 * t;
            float b0 = bias[cc], b1 = bias[cc + 1];
            float v0 = acc[mt][nt][0] + b0, v1 = acc[mt][nt][1] + b1;
            float v2 = acc[mt][nt][2] + b0, v3 = acc[mt][nt][3] + b1;
            if (SPLIT_OUT) {
                uint32_t h01, l01, h23, l23;
                packsplit(v0, v1, h01, l01);
                packsplit(v2, v3, h23, l23);
                *(uint32_t*)(Ch + (size_t)r0 * N + cc)       = h01;
                *(uint32_t*)(Cl + (size_t)r0 * N + cc)       = l01;
                *(uint32_t*)(Ch + (size_t)(r0 + 8) * N + cc) = h23;
                *(uint32_t*)(Cl + (size_t)(r0 + 8) * N + cc) = l23;
            } else {
                *(float2*)(C + (size_t)r0 * N + cc)       = make_float2(v0, v1);
                *(float2*)(C + (size_t)(r0 + 8) * N + cc) = make_float2(v2, v3);
            }
        }
    }
}

// ---------------------------------------------------------------------------
// Flash attention, fp16 (R12 version, unchanged). Block = 128 queries.
// QK: 2x (qh.kh + ql.kh). PV: 1x. KV: 2 arrays double-buffered. 2 CTAs/SM.
// ---------------------------------------------------------------------------
#define KSTR 72
#define FTE  (64 * KSTR)
#define FTB  (FTE * 2)
#define QTE  (128 * KSTR)
#define QTB  (QTE * 2)

__global__ __launch_bounds__(256, 2) void flash_h16_kernel(
    const h16* __restrict__ qkvh, const h16* __restrict__ qkvl,
    h16* __restrict__ attnh, h16* __restrict__ attnl)
{
    extern __shared__ h16 smf[];
    const uint32_t sm0 = smem_u32(smf);

    const int tid = threadIdx.x;
    const int lane = tid & 31, wid = tid >> 5;
    const int g = lane >> 2, t = lane & 3;

    const int bq = gridDim.x - 1 - blockIdx.x;
    const int q0 = bq * 128;
    const int bh_ = blockIdx.y;
    const int b = bh_ / HH, h = bh_ % HH;
    const int J = 2 * bq + 1;

    const h16* Qh_s = smf + 4 * FTE;
    const h16* Ql_s = Qh_s + QTE;
    const uint32_t qsm_h = sm0 + 4 * FTB;
    const uint32_t qsm_l = qsm_h + QTB;

    // ---- stage Q (hi/lo) ----
    {
        const int tok0 = (b * SS + q0) * NQKV + h * HDD;
        #pragma unroll
        for (int i = 0; i < 4; i++) {
            int idx = tid + i * 256;
            int r = idx >> 3, c = idx & 7;
            uint32_t doff = r * 144 + c * 16;
            int src = tok0 + r * NQKV + c * 8;
            cp16(qsm_h + doff, qkvh + src);
            cp16(qsm_l + doff, qkvl + src);
        }
        CP_COMMIT();
    }

    const int qrow = q0 + wid * 16 + g;

    float od[8][4];
    #pragma unroll
    for (int nt = 0; nt < 8; nt++)
        #pragma unroll
        for (int r = 0; r < 4; r++) od[nt][r] = 0.f;
    float m0v = -1e30f, m1v = -1e30f, l0v = 0.f, l1v = 0.f;

    auto stage = [&](int j) {
        const uint32_t bb = sm0 + (j & 1) * 2 * FTB;
        const int tok0 = (b * SS + j * 64) * NQKV + DD + h * HDD;
        #pragma unroll
        for (int i = 0; i < 2; i++) {
            int idx = tid + i * 256;
            int r = idx >> 3, c = idx & 7;
            uint32_t doff = r * 144 + c * 16;
            int sK = tok0 + r * NQKV + c * 8;
            int sV = sK + DD;
            cp16(bb + doff,       qkvh + sK);   // Kh
            cp16(bb + FTB + doff, qkvh + sV);   // Vh
        }
        CP_COMMIT();
    };

    stage(0);
    const float CLOG = 0.18033688011112042f;   // 0.125 * log2(e)

    for (int j = 0; j <= J; j++) {
        if (j < J) stage(j + 1);
        if (j < J) { CP_WAIT1(); } else { CP_WAIT0(); }
        __syncthreads();

        const h16* Kh_s = smf + (size_t)(j & 1) * 2 * FTE;
        const uint32_t vh_base = sm0 + (j & 1) * 2 * FTB + FTB;

        // ---- S = Q @ K^T (2x fp16: qh.kh + ql.kh) ----
        float sc[8][4];
        #pragma unroll
        for (int nt = 0; nt < 8; nt++)
            #pragma unroll
            for (int r = 0; r < 4; r++) sc[nt][r] = 0.f;

        #pragma unroll
        for (int s = 0; s < 4; s++) {
            const int k0 = s * 16;
            const h16* qr_h = Qh_s + (wid * 16 + g) * KSTR + k0 + 2 * t;
            uint32_t qh0 = *(const uint32_t*)qr_h;
            uint32_t qh1 = *(const uint32_t*)(qr_h + 8 * KSTR);
            uint32_t qh2 = *(const uint32_t*)(qr_h + 8);
            uint32_t qh3 = *(const uint32_t*)(qr_h + 8 * KSTR + 8);
            const h16* qr_l = Ql_s + (wid * 16 + g) * KSTR + k0 + 2 * t;
            uint32_t ql0 = *(const uint32_t*)qr_l;
            uint32_t ql1 = *(const uint32_t*)(qr_l + 8 * KSTR);
            uint32_t ql2 = *(const uint32_t*)(qr_l + 8);
            uint32_t ql3 = *(const uint32_t*)(qr_l + 8 * KSTR + 8);
            #pragma unroll
            for (int nt = 0; nt < 8; nt++) {
                const h16* kr = Kh_s + (nt * 8 + g) * KSTR + k0 + 2 * t;
                uint32_t b0h = *(const uint32_t*)kr;
                uint32_t b1h = *(const uint32_t*)(kr + 8);
                mma16816(sc[nt], qh0, qh1, qh2, qh3, b0h, b1h);
                mma16816(sc[nt], ql0, ql1, ql2, ql3, b0h, b1h);
            }
        }

        // ---- scale + mask + online softmax (base-2) ----
        const bool maskTile = (j >= 2 * bq);
        const int key_base = j * 64;
        float tmax0 = -1e30f, tmax1 = -1e30f;
        #pragma unroll
        for (int nt = 0; nt < 8; nt++) {
            #pragma unroll
            for (int i = 0; i < 4; i++) {
                float v = sc[nt][i] * CLOG;
                if (maskTile) {
                    int key = key_base + nt * 8 + 2 * t + (i & 1);
                    int qq = qrow + ((i >= 2) ? 8 : 0);
                    if (key > qq) v = -1e30f;
                }
                sc[nt][i] = v;
                if (i < 2) tmax0 = fmaxf(tmax0, v);
                else       tmax1 = fmaxf(tmax1, v);
            }
        }
        tmax0 = fmaxf(tmax0, __shfl_xor_sync(0xffffffffu, tmax0, 1));
        tmax0 = fmaxf(tmax0, __shfl_xor_sync(0xffffffffu, tmax0, 2));
        tmax1 = fmaxf(tmax1, __shfl_xor_sync(0xffffffffu, tmax1, 1));
        tmax1 = fmaxf(tmax1, __shfl_xor_sync(0xffffffffu, tmax1, 2));

        float mn0 = fmaxf(m0v, tmax0), mn1 = fmaxf(m1v, tmax1);
        float a0 = ex2f(m0v - mn0), a1 = ex2f(m1v - mn1);
        m0v = mn0; m1v = mn1;

        float s0 = 0.f, s1 = 0.f;
        #pragma unroll
        for (int nt = 0; nt < 8; nt++) {
            float p0 = ex2f(sc[nt][0] - mn0);
            float p1 = ex2f(sc[nt][1] - mn0);
            float p2 = ex2f(sc[nt][2] - mn1);
            float p3 = ex2f(sc[nt][3] - mn1);
            sc[nt][0] = p0; sc[nt][1] = p1; sc[nt][2] = p2; sc[nt][3] = p3;
            s0 += p0 + p1; s1 += p2 + p3;
        }
        s0 += __shfl_xor_sync(0xffffffffu, s0, 1);
        s0 += __shfl_xor_sync(0xffffffffu, s0, 2);
        s1 += __shfl_xor_sync(0xffffffffu, s1, 1);
        s1 += __shfl_xor_sync(0xffffffffu, s1, 2);
        l0v = l0v * a0 + s0;
        l1v = l1v * a1 + s1;

        #pragma unroll
        for (int nt = 0; nt < 8; nt++) {
            od[nt][0] *= a0; od[nt][1] *= a0;
            od[nt][2] *= a1; od[nt][3] *= a1;
        }

        // ---- pack P into plain fp16 A-fragments (1x PV) ----
        uint32_t ph[4][4];
        #pragma unroll
        for (int s2 = 0; s2 < 4; s2++) {
            int e = 2 * s2, o = 2 * s2 + 1;
            ph[s2][0] = packh(sc[e][0], sc[e][1]);
            ph[s2][1] = packh(sc[e][2], sc[e][3]);
            ph[s2][2] = packh(sc[o][0], sc[o][1]);
            ph[s2][3] = packh(sc[o][2], sc[o][3]);
        }

        // ---- O += P @ V (single pass, V hi via ldmatrix.trans) ----
        #pragma unroll
        for (int s2 = 0; s2 < 4; s2++) {
            uint32_t rowcol = (s2 * 16 + (lane & 15)) * 144 + ((lane & 16) ? 16 : 0);
            #pragma unroll
            for (int dtb = 0; dtb < 4; dtb++) {
                uint32_t addr = vh_base + rowcol + dtb * 32;
                uint32_t vh4[4];
                ldsm4t(vh4, addr);
                mma16816(od[2 * dtb],     ph[s2][0], ph[s2][1], ph[s2][2], ph[s2][3], vh4[0], vh4[1]);
                mma16816(od[2 * dtb + 1], ph[s2][0], ph[s2][1], ph[s2][2], ph[s2][3], vh4[2], vh4[3]);
            }
        }
        __syncthreads();
    }

    // ---- epilogue: normalize, split, write attn hi/lo ----
    float inv0 = 1.f / l0v, inv1 = 1.f / l1v;
    h16* oh = attnh + (size_t)(b * SS + qrow) * DD + h * HDD;
    h16* ol = attnl + (size_t)(b * SS + qrow) * DD + h * HDD;
    #pragma unroll
    for (int nt = 0; nt < 8; nt++) {
        int cc = nt * 8 + 2 * t;
        float v0 = od[nt][0] * inv0, v1 = od[nt][1] * inv0;
        float v2 = od[nt][2] * inv1, v3 = od[nt][3] * inv1;
        uint32_t h01, l01, h23, l23;
        packsplit(v0, v1, h01, l01);
        packsplit(v2, v3, h23, l23);
        *(uint32_t*)(oh + cc)          = h01;
        *(uint32_t*)(ol + cc)          = l01;
        *(uint32_t*)(oh + 8 * DD + cc) = h23;
        *(uint32_t*)(ol + 8 * DD + cc) = l23;
    }
}

// ---------------------------------------------------------------------------
// Launch
// ---------------------------------------------------------------------------
extern "C" void kernel_launch(void* const* d_in, const int* in_sizes, int n_in,
                              void* d_out, int out_size)
{
    const float* X    = (const float*)d_in[0];
    const float* Wqkv = (const float*)d_in[1];
    const float* bqkv = (const float*)d_in[2];
    const float* Wout = (const float*)d_in[3];
    const float* bout = (const float*)d_in[4];
    float* out = (float*)d_out;

    h16 *qkvh, *qkvl, *attnh, *attnl, *Xh, *Xl, *Bqh, *Bql, *Boh, *Bol;
    cudaGetSymbolAddress((void**)&qkvh,  g_qkvh);
    cudaGetSymbolAddress((void**)&qkvl,  g_qkvl);
    cudaGetSymbolAddress((void**)&attnh, g_attnh);
    cudaGetSymbolAddress((void**)&attnl, g_attnl);
    cudaGetSymbolAddress((void**)&Xh,    g_Xh);
    cudaGetSymbolAddress((void**)&Xl,    g_Xl);
    cudaGetSymbolAddress((void**)&Bqh,   g_Bqh);
    cudaGetSymbolAddress((void**)&Bql,   g_Bql);
    cudaGetSymbolAddress((void**)&Boh,   g_Boh);
    cudaGetSymbolAddress((void**)&Bol,   g_Bol);

    const int gemm_smem  = 2 * 4 * ABYTES;            // 81920
    const int flash_smem = 4 * FTB + 2 * QTB;         // 73728

    cudaFuncSetAttribute((const void*)gemm_h16_kernel<true, 1>,
                         cudaFuncAttributeMaxDynamicSharedMemorySize, gemm_smem);
    cudaFuncSetAttribute((const void*)gemm_h16_kernel<false, 2>,
                         cudaFuncAttributeMaxDynamicSharedMemorySize, gemm_smem);
    cudaFuncSetAttribute((const void*)flash_h16_kernel,
                         cudaFuncAttributeMaxDynamicSharedMemorySize, flash_smem);

    // Prep
    {
        int n4 = MM * DD / 4;
        split_pair_kernel<<<(n4 + 255) / 256, 256>>>(X, Xh, Xl, n4);
        dim3 blk(32, 8);
        transpose_split_kernel<<<dim3(NQKV / 32, DD / 32), blk>>>(Wqkv, Bqh, Bql, DD, NQKV);
        transpose_split_kernel<<<dim3(DD / 32, DD / 32), blk>>>(Wout, Boh, Bol, DD, DD);
    }

    // 1) QKV = X @ Wqkv + bqkv   (1x fp16: xh.wh; epilogue splits fp32 acc)
    {
        dim3 grid(NQKV / 128, MM / 128);
        gemm_h16_kernel<true, 1><<<grid, 256, gemm_smem>>>(
            Xh, Xl, Bqh, Bql, bqkv, nullptr, qkvh, qkvl, MM, NQKV, DD);
    }

    // 2) Flash attention (QK 2x, PV 1x)
    {
        dim3 grid(SS / 128, BB * HH);
        flash_h16_kernel<<<grid, 256, flash_smem>>>(qkvh, qkvl, attnh, attnl);
    }

    // 3) out = attn @ Wout + bout  (2x fp16)
    {
        dim3 grid(DD / 128, MM / 128);
        gemm_h16_kernel<false, 2><<<grid, 256, gemm_smem>>>(
            attnh, attnl, Boh, Bol, bout, out, nullptr, nullptr, MM, DD, DD);
    }
}

// round 17
// speedup vs baseline: 1.4290x; 1.4290x over previous
#include <cuda_runtime.h>
#include <cuda_fp16.h>
#include <math.h>
#include <cstdint>

// Problem constants
#define BB   2
#define SS   2048
#define DD   768
#define HH   12
#define HDD  64
#define MM   (BB * SS)        // 4096
#define NQKV (3 * DD)         // 2304

typedef __half h16;

// Scratch (__device__ globals; no allocation allowed)
__device__ h16 g_qkvh[MM * NQKV];
__device__ h16 g_qkvl[MM * NQKV];
__device__ h16 g_attnh[MM * DD];
__device__ h16 g_attnl[MM * DD];
__device__ h16 g_Xh[MM * DD];
__device__ h16 g_Xl[MM * DD];
__device__ h16 g_Bqh[NQKV * DD];
__device__ h16 g_Bql[NQKV * DD];
__device__ h16 g_Boh[DD * DD];
__device__ h16 g_Bol[DD * DD];

// ---------------------------------------------------------------------------
// Helpers
// ---------------------------------------------------------------------------
__device__ __forceinline__ uint32_t smem_u32(const void* p) {
    uint32_t a;
    asm("{ .reg .u64 t; cvta.to.shared.u64 t, %1; cvt.u32.u64 %0, t; }" : "=r"(a) : "l"(p));
    return a;
}

__device__ __forceinline__ float ex2f(float x) {
    float r;
    asm("ex2.approx.ftz.f32 %0, %1;" : "=f"(r) : "f"(x));
    return r;
}

// pack two floats into fp16x2 (x0 -> lower 16 bits)
__device__ __forceinline__ uint32_t packh(float x0, float x1) {
    __half2 h = __floats2half2_rn(x0, x1);
    return *(uint32_t*)&h;
}

// fp16 hi/lo split of a float pair (hi = rn(x), lo = rn(x - hi))
__device__ __forceinline__ void packsplit(float x0, float x1, uint32_t& hi, uint32_t& lo) {
    __half2 h = __floats2half2_rn(x0, x1);
    hi = *(uint32_t*)&h;
    float2 f = __half22float2(h);
    __half2 l = __floats2half2_rn(x0 - f.x, x1 - f.y);
    lo = *(uint32_t*)&l;
}

__device__ __forceinline__ void mma16816(float* c,
                                         uint32_t a0, uint32_t a1, uint32_t a2, uint32_t a3,
                                         uint32_t b0, uint32_t b1) {
    asm volatile(
        "mma.sync.aligned.m16n8k16.row.col.f32.f16.f16.f32 "
        "{%0,%1,%2,%3}, {%4,%5,%6,%7}, {%8,%9}, {%0,%1,%2,%3};\n"
        : "+f"(c[0]), "+f"(c[1]), "+f"(c[2]), "+f"(c[3])
        : "r"(a0), "r"(a1), "r"(a2), "r"(a3), "r"(b0), "r"(b1));
}

__device__ __forceinline__ void ldsm4t(uint32_t* r, uint32_t saddr) {
    asm volatile("ldmatrix.sync.aligned.m8n8.x4.trans.shared.b16 {%0,%1,%2,%3}, [%4];"
                 : "=r"(r[0]), "=r"(r[1]), "=r"(r[2]), "=r"(r[3]) : "r"(saddr));
}

__device__ __forceinline__ void cp16(uint32_t dst, const void* src) {
    asm volatile("cp.async.cg.shared.global [%0], [%1], 16;" :: "r"(dst), "l"(src));
}
#define CP_COMMIT() asm volatile("cp.async.commit_group;" ::: "memory")
#define CP_WAIT0()  asm volatile("cp.async.wait_group 0;" ::: "memory")
#define CP_WAIT1()  asm volatile("cp.async.wait_group 1;" ::: "memory")

// ---------------------------------------------------------------------------
// Prep kernels
// ---------------------------------------------------------------------------
__global__ void split_pair_kernel(const float* __restrict__ x,
                                  h16* __restrict__ h, h16* __restrict__ l, int n4)
{
    int i = blockIdx.x * blockDim.x + threadIdx.x;
    if (i < n4) {
        float4 v = ((const float4*)x)[i];
        uint32_t h01, l01, h23, l23;
        packsplit(v.x, v.y, h01, l01);
        packsplit(v.z, v.w, h23, l23);
        ((uint2*)h)[i] = make_uint2(h01, h23);
        ((uint2*)l)[i] = make_uint2(l01, l23);
    }
}

__global__ void transpose_split_kernel(const float* __restrict__ W,
                                       h16* __restrict__ Th, h16* __restrict__ Tl,
                                       int Kd, int Nd)
{
    __shared__ float tile[32][33];
    int n0 = blockIdx.x * 32, k0 = blockIdx.y * 32;
    int tx = threadIdx.x, ty = threadIdx.y;   // (32, 8)
    #pragma unroll
    for (int i = 0; i < 4; i++)
        tile[ty + i * 8][tx] = W[(size_t)(k0 + ty + i * 8) * Nd + n0 + tx];
    __syncthreads();
    int idx = ty * 32 + tx;
    int n = idx >> 3, kp = idx & 7;
    #pragma unroll
    for (int w = 0; w < 2; w++) {
        int k2 = (kp + w * 8) * 2;
        uint32_t hh, ll;
        packsplit(tile[k2][n], tile[k2 + 1][n], hh, ll);
        *(uint32_t*)(Th + (size_t)(n0 + n) * Kd + k0 + k2) = hh;
        *(uint32_t*)(Tl + (size_t)(n0 + n) * Kd + k0 + k2) = ll;
    }
}

// ---------------------------------------------------------------------------
// GEMM (fp16 compensated): C[M,N] = A[M,K] @ Bt[N,K]^T + bias
// R7-proven pipeline: 128x128 block, K-chunk 32, double buffer, scalar LDS
// fragment loads (stride 40, bank-clean), 2 syncs/chunk, 2 CTAs/SM.
// PASSES = 3: hh + hl + lh; PASSES = 2: hh + lh; PASSES = 1: hh only.
// ---------------------------------------------------------------------------
#define ASTR 40
#define TILEE (128 * ASTR)
#define ABYTES (TILEE * 2)

template<bool SPLIT_OUT, int PASSES>
__global__ __launch_bounds__(256, 2) void gemm_h16_kernel(
    const h16* __restrict__ Ah_g, const h16* __restrict__ Al_g,
    const h16* __restrict__ Bh_g, const h16* __restrict__ Bl_g,
    const float* __restrict__ bias,
    float* __restrict__ C, h16* __restrict__ Ch, h16* __restrict__ Cl,
    int M, int N, int K)
{
    extern __shared__ h16 smb[];
    const uint32_t sm0 = smem_u32(smb);

    const int tid = threadIdx.x;
    const int lane = tid & 31, warp = tid >> 5;
    const int g = lane >> 2, t = lane & 3;
    const int m0 = blockIdx.y * 128, n0 = blockIdx.x * 128;
    const int wm = (warp >> 2) * 64, wn = (warp & 3) * 32;

    float acc[4][4][4];
    #pragma unroll
    for (int mt = 0; mt < 4; mt++)
        #pragma unroll
        for (int nt = 0; nt < 4; nt++)
            #pragma unroll
            for (int r = 0; r < 4; r++) acc[mt][nt][r] = 0.f;

    const int NCH = K / 32;

    auto stage = [&](int ch) {
        const int kb = ch * 32;
        const uint32_t bb = sm0 + (ch & 1) * 4 * ABYTES;
        #pragma unroll
        for (int i = 0; i < 2; i++) {
            int idx = tid + i * 256;
            int r = idx >> 2, cc = idx & 3;
            uint32_t doff = r * 80 + cc * 16;
            cp16(bb + doff,              Ah_g + (size_t)(m0 + r) * K + kb + cc * 8);
            if (PASSES >= 2)
                cp16(bb + ABYTES + doff, Al_g + (size_t)(m0 + r) * K + kb + cc * 8);
            cp16(bb + 2 * ABYTES + doff, Bh_g + (size_t)(n0 + r) * K + kb + cc * 8);
            if (PASSES == 3)
                cp16(bb + 3 * ABYTES + doff, Bl_g + (size_t)(n0 + r) * K + kb + cc * 8);
        }
        CP_COMMIT();
    };

    stage(0);
    stage(1);

    for (int c = 0; c < NCH; c++) {
        if (c == NCH - 1) { CP_WAIT0(); } else { CP_WAIT1(); }
        __syncthreads();

        const h16* bA_h = smb + (size_t)(c & 1) * 4 * TILEE;
        const h16* bA_l = bA_h + TILEE;
        const h16* bB_h = bA_h + 2 * TILEE;
        const h16* bB_l = bA_h + 3 * TILEE;

        #pragma unroll
        for (int st = 0; st < 2; st++) {
            const int k0 = st * 16;
            uint32_t bh[4][2], bl[4][2];
            #pragma unroll
            for (int nt = 0; nt < 4; nt++) {
                const h16* kr = bB_h + (wn + nt * 8 + g) * ASTR + k0 + 2 * t;
                bh[nt][0] = *(const uint32_t*)kr;
                bh[nt][1] = *(const uint32_t*)(kr + 8);
                if (PASSES == 3) {
                    const h16* kl = bB_l + (wn + nt * 8 + g) * ASTR + k0 + 2 * t;
                    bl[nt][0] = *(const uint32_t*)kl;
                    bl[nt][1] = *(const uint32_t*)(kl + 8);
                }
            }
            #pragma unroll
            for (int mt = 0; mt < 4; mt++) {
                const h16* ar = bA_h + (wm + mt * 16 + g) * ASTR + k0 + 2 * t;
                uint32_t ah0 = *(const uint32_t*)ar;
                uint32_t ah1 = *(const uint32_t*)(ar + 8 * ASTR);
                uint32_t ah2 = *(const uint32_t*)(ar + 8);
                uint32_t ah3 = *(const uint32_t*)(ar + 8 * ASTR + 8);
                uint32_t al0 = 0, al1 = 0, al2 = 0, al3 = 0;
                if (PASSES >= 2) {
                    const h16* al = bA_l + (wm + mt * 16 + g) * ASTR + k0 + 2 * t;
                    al0 = *(const uint32_t*)al;
                    al1 = *(const uint32_t*)(al + 8 * ASTR);
                    al2 = *(const uint32_t*)(al + 8);
                    al3 = *(const uint32_t*)(al + 8 * ASTR + 8);
                }
                #pragma unroll
                for (int nt = 0; nt < 4; nt++) {
                    mma16816(acc[mt][nt], ah0, ah1, ah2, ah3, bh[nt][0], bh[nt][1]);
                    if (PASSES == 3)
                        mma16816(acc[mt][nt], ah0, ah1, ah2, ah3, bl[nt][0], bl[nt][1]);
                    if (PASSES >= 2)
                        mma16816(acc[mt][nt], al0, al1, al2, al3, bh[nt][0], bh[nt][1]);
                }
            }
        }
        __syncthreads();
        if (c + 2 < NCH) stage(c + 2);
    }

    #pragma unroll
    for (int mt = 0; mt < 4; mt++) {
        int r0 = m0 + wm + mt * 16 + g;
        #pragma unroll
        for (int nt = 0; nt < 4; nt++) {
            int cc = n0 + wn + nt * 8 + 2 * t;
            float b0 = bias[cc], b1 = bias[cc + 1];
            float v0 = acc[mt][nt][0] + b0, v1 = acc[mt][nt][1] + b1;
            float v2 = acc[mt][nt][2] + b0, v3 = acc[mt][nt][3] + b1;
            if (SPLIT_OUT) {
                uint32_t h01, l01, h23, l23;
                packsplit(v0, v1, h01, l01);
                packsplit(v2, v3, h23, l23);
                *(uint32_t*)(Ch + (size_t)r0 * N + cc)       = h01;
                *(uint32_t*)(Cl + (size_t)r0 * N + cc)       = l01;
                *(uint32_t*)(Ch + (size_t)(r0 + 8) * N + cc) = h23;
                *(uint32_t*)(Cl + (size_t)(r0 + 8) * N + cc) = l23;
            } else {
                *(float2*)(C + (size_t)r0 * N + cc)       = make_float2(v0, v1);
                *(float2*)(C + (size_t)(r0 + 8) * N + cc) = make_float2(v2, v3);
            }
        }
    }
}

// ---------------------------------------------------------------------------
// Flash attention, fp16 (R12 version, unchanged). Block = 128 queries.
// QK: 2x (qh.kh + ql.kh). PV: 1x. KV: 2 arrays double-buffered. 2 CTAs/SM.
// ---------------------------------------------------------------------------
#define KSTR 72
#define FTE  (64 * KSTR)
#define FTB  (FTE * 2)
#define QTE  (128 * KSTR)
#define QTB  (QTE * 2)

__global__ __launch_bounds__(256, 2) void flash_h16_kernel(
    const h16* __restrict__ qkvh, const h16* __restrict__ qkvl,
    h16* __restrict__ attnh, h16* __restrict__ attnl)
{
    extern __shared__ h16 smf[];
    const uint32_t sm0 = smem_u32(smf);

    const int tid = threadIdx.x;
    const int lane = tid & 31, wid = tid >> 5;
    const int g = lane >> 2, t = lane & 3;

    const int bq = gridDim.x - 1 - blockIdx.x;
    const int q0 = bq * 128;
    const int bh_ = blockIdx.y;
    const int b = bh_ / HH, h = bh_ % HH;
    const int J = 2 * bq + 1;

    const h16* Qh_s = smf + 4 * FTE;
    const h16* Ql_s = Qh_s + QTE;
    const uint32_t qsm_h = sm0 + 4 * FTB;
    const uint32_t qsm_l = qsm_h + QTB;

    // ---- stage Q (hi/lo) ----
    {
        const int tok0 = (b * SS + q0) * NQKV + h * HDD;
        #pragma unroll
        for (int i = 0; i < 4; i++) {
            int idx = tid + i * 256;
            int r = idx >> 3, c = idx & 7;
            uint32_t doff = r * 144 + c * 16;
            int src = tok0 + r * NQKV + c * 8;
            cp16(qsm_h + doff, qkvh + src);
            cp16(qsm_l + doff, qkvl + src);
        }
        CP_COMMIT();
    }

    const int qrow = q0 + wid * 16 + g;

    float od[8][4];
    #pragma unroll
    for (int nt = 0; nt < 8; nt++)
        #pragma unroll
        for (int r = 0; r < 4; r++) od[nt][r] = 0.f;
    float m0v = -1e30f, m1v = -1e30f, l0v = 0.f, l1v = 0.f;

    auto stage = [&](int j) {
        const uint32_t bb = sm0 + (j & 1) * 2 * FTB;
        const int tok0 = (b * SS + j * 64) * NQKV + DD + h * HDD;
        #pragma unroll
        for (int i = 0; i < 2; i++) {
            int idx = tid + i * 256;
            int r = idx >> 3, c = idx & 7;
            uint32_t doff = r * 144 + c * 16;
            int sK = tok0 + r * NQKV + c * 8;
            int sV = sK + DD;
            cp16(bb + doff,       qkvh + sK);   // Kh
            cp16(bb + FTB + doff, qkvh + sV);   // Vh
        }
        CP_COMMIT();
    };

    stage(0);
    const float CLOG = 0.18033688011112042f;   // 0.125 * log2(e)

    for (int j = 0; j <= J; j++) {
        if (j < J) stage(j + 1);
        if (j < J) { CP_WAIT1(); } else { CP_WAIT0(); }
        __syncthreads();

        const h16* Kh_s = smf + (size_t)(j & 1) * 2 * FTE;
        const uint32_t vh_base = sm0 + (j & 1) * 2 * FTB + FTB;

        // ---- S = Q @ K^T (2x fp16: qh.kh + ql.kh) ----
        float sc[8][4];
        #pragma unroll
        for (int nt = 0; nt < 8; nt++)
            #pragma unroll
            for (int r = 0; r < 4; r++) sc[nt][r] = 0.f;

        #pragma unroll
        for (int s = 0; s < 4; s++) {
            const int k0 = s * 16;
            const h16* qr_h = Qh_s + (wid * 16 + g) * KSTR + k0 + 2 * t;
            uint32_t qh0 = *(const uint32_t*)qr_h;
            uint32_t qh1 = *(const uint32_t*)(qr_h + 8 * KSTR);
            uint32_t qh2 = *(const uint32_t*)(qr_h + 8);
            uint32_t qh3 = *(const uint32_t*)(qr_h + 8 * KSTR + 8);
            const h16* qr_l = Ql_s + (wid * 16 + g) * KSTR + k0 + 2 * t;
            uint32_t ql0 = *(const uint32_t*)qr_l;
            uint32_t ql1 = *(const uint32_t*)(qr_l + 8 * KSTR);
            uint32_t ql2 = *(const uint32_t*)(qr_l + 8);
            uint32_t ql3 = *(const uint32_t*)(qr_l + 8 * KSTR + 8);
            #pragma unroll
            for (int nt = 0; nt < 8; nt++) {
                const h16* kr = Kh_s + (nt * 8 + g) * KSTR + k0 + 2 * t;
                uint32_t b0h = *(const uint32_t*)kr;
                uint32_t b1h = *(const uint32_t*)(kr + 8);
                mma16816(sc[nt], qh0, qh1, qh2, qh3, b0h, b1h);
                mma16816(sc[nt], ql0, ql1, ql2, ql3, b0h, b1h);
            }
        }

        // ---- scale + mask + online softmax (base-2) ----
        const bool maskTile = (j >= 2 * bq);
        const int key_base = j * 64;
        float tmax0 = -1e30f, tmax1 = -1e30f;
        #pragma unroll
        for (int nt = 0; nt < 8; nt++) {
            #pragma unroll
            for (int i = 0; i < 4; i++) {
                float v = sc[nt][i] * CLOG;
                if (maskTile) {
                    int key = key_base + nt * 8 + 2 * t + (i & 1);
                    int qq = qrow + ((i >= 2) ? 8 : 0);
                    if (key > qq) v = -1e30f;
                }
                sc[nt][i] = v;
                if (i < 2) tmax0 = fmaxf(tmax0, v);
                else       tmax1 = fmaxf(tmax1, v);
            }
        }
        tmax0 = fmaxf(tmax0, __shfl_xor_sync(0xffffffffu, tmax0, 1));
        tmax0 = fmaxf(tmax0, __shfl_xor_sync(0xffffffffu, tmax0, 2));
        tmax1 = fmaxf(tmax1, __shfl_xor_sync(0xffffffffu, tmax1, 1));
        tmax1 = fmaxf(tmax1, __shfl_xor_sync(0xffffffffu, tmax1, 2));

        float mn0 = fmaxf(m0v, tmax0), mn1 = fmaxf(m1v, tmax1);
        float a0 = ex2f(m0v - mn0), a1 = ex2f(m1v - mn1);
        m0v = mn0; m1v = mn1;

        float s0 = 0.f, s1 = 0.f;
        #pragma unroll
        for (int nt = 0; nt < 8; nt++) {
            float p0 = ex2f(sc[nt][0] - mn0);
            float p1 = ex2f(sc[nt][1] - mn0);
            float p2 = ex2f(sc[nt][2] - mn1);
            float p3 = ex2f(sc[nt][3] - mn1);
            sc[nt][0] = p0; sc[nt][1] = p1; sc[nt][2] = p2; sc[nt][3] = p3;
            s0 += p0 + p1; s1 += p2 + p3;
        }
        s0 += __shfl_xor_sync(0xffffffffu, s0, 1);
        s0 += __shfl_xor_sync(0xffffffffu, s0, 2);
        s1 += __shfl_xor_sync(0xffffffffu, s1, 1);
        s1 += __shfl_xor_sync(0xffffffffu, s1, 2);
        l0v = l0v * a0 + s0;
        l1v = l1v * a1 + s1;

        #pragma unroll
        for (int nt = 0; nt < 8; nt++) {
            od[nt][0] *= a0; od[nt][1] *= a0;
            od[nt][2] *= a1; od[nt][3] *= a1;
        }

        // ---- pack P into plain fp16 A-fragments (1x PV) ----
        uint32_t ph[4][4];
        #pragma unroll
        for (int s2 = 0; s2 < 4; s2++) {
            int e = 2 * s2, o = 2 * s2 + 1;
            ph[s2][0] = packh(sc[e][0], sc[e][1]);
            ph[s2][1] = packh(sc[e][2], sc[e][3]);
            ph[s2][2] = packh(sc[o][0], sc[o][1]);
            ph[s2][3] = packh(sc[o][2], sc[o][3]);
        }

        // ---- O += P @ V (single pass, V hi via ldmatrix.trans) ----
        #pragma unroll
        for (int s2 = 0; s2 < 4; s2++) {
            uint32_t rowcol = (s2 * 16 + (lane & 15)) * 144 + ((lane & 16) ? 16 : 0);
            #pragma unroll
            for (int dtb = 0; dtb < 4; dtb++) {
                uint32_t addr = vh_base + rowcol + dtb * 32;
                uint32_t vh4[4];
                ldsm4t(vh4, addr);
                mma16816(od[2 * dtb],     ph[s2][0], ph[s2][1], ph[s2][2], ph[s2][3], vh4[0], vh4[1]);
                mma16816(od[2 * dtb + 1], ph[s2][0], ph[s2][1], ph[s2][2], ph[s2][3], vh4[2], vh4[3]);
            }
        }
        __syncthreads();
    }

    // ---- epilogue: normalize, split, write attn hi/lo ----
    float inv0 = 1.f / l0v, inv1 = 1.f / l1v;
    h16* oh = attnh + (size_t)(b * SS + qrow) * DD + h * HDD;
    h16* ol = attnl + (size_t)(b * SS + qrow) * DD + h * HDD;
    #pragma unroll
    for (int nt = 0; nt < 8; nt++) {
        int cc = nt * 8 + 2 * t;
        float v0 = od[nt][0] * inv0, v1 = od[nt][1] * inv0;
        float v2 = od[nt][2] * inv1, v3 = od[nt][3] * inv1;
        uint32_t h01, l01, h23, l23;
        packsplit(v0, v1, h01, l01);
        packsplit(v2, v3, h23, l23);
        *(uint32_t*)(oh + cc)          = h01;
        *(uint32_t*)(ol + cc)          = l01;
        *(uint32_t*)(oh + 8 * DD + cc) = h23;
        *(uint32_t*)(ol + 8 * DD + cc) = l23;
    }
}

// ---------------------------------------------------------------------------
// Launch
// ---------------------------------------------------------------------------
extern "C" void kernel_launch(void* const* d_in, const int* in_sizes, int n_in,
                              void* d_out, int out_size)
{
    const float* X    = (const float*)d_in[0];
    const float* Wqkv = (const float*)d_in[1];
    const float* bqkv = (const float*)d_in[2];
    const float* Wout = (const float*)d_in[3];
    const float* bout = (const float*)d_in[4];
    float* out = (float*)d_out;

    h16 *qkvh, *qkvl, *attnh, *attnl, *Xh, *Xl, *Bqh, *Bql, *Boh, *Bol;
    cudaGetSymbolAddress((void**)&qkvh,  g_qkvh);
    cudaGetSymbolAddress((void**)&qkvl,  g_qkvl);
    cudaGetSymbolAddress((void**)&attnh, g_attnh);
    cudaGetSymbolAddress((void**)&attnl, g_attnl);
    cudaGetSymbolAddress((void**)&Xh,    g_Xh);
    cudaGetSymbolAddress((void**)&Xl,    g_Xl);
    cudaGetSymbolAddress((void**)&Bqh,   g_Bqh);
    cudaGetSymbolAddress((void**)&Bql,   g_Bql);
    cudaGetSymbolAddress((void**)&Boh,   g_Boh);
    cudaGetSymbolAddress((void**)&Bol,   g_Bol);

    const int gemm_smem  = 2 * 4 * ABYTES;            // 81920
    const int flash_smem = 4 * FTB + 2 * QTB;         // 73728

    cudaFuncSetAttribute((const void*)gemm_h16_kernel<true, 2>,
                         cudaFuncAttributeMaxDynamicSharedMemorySize, gemm_smem);
    cudaFuncSetAttribute((const void*)gemm_h16_kernel<false, 1>,
                         cudaFuncAttributeMaxDynamicSharedMemorySize, gemm_smem);
    cudaFuncSetAttribute((const void*)flash_h16_kernel,
                         cudaFuncAttributeMaxDynamicSharedMemorySize, flash_smem);

    // Prep
    {
        int n4 = MM * DD / 4;
        split_pair_kernel<<<(n4 + 255) / 256, 256>>>(X, Xh, Xl, n4);
        dim3 blk(32, 8);
        transpose_split_kernel<<<dim3(NQKV / 32, DD / 32), blk>>>(Wqkv, Bqh, Bql, DD, NQKV);
        transpose_split_kernel<<<dim3(DD / 32, DD / 32), blk>>>(Wout, Boh, Bol, DD, DD);
    }

    // 1) QKV = X @ Wqkv + bqkv   (2x fp16: xh.wh + xl.wh — R12 config)
    {
        dim3 grid(NQKV / 128, MM / 128);
        gemm_h16_kernel<true, 2><<<grid, 256, gemm_smem>>>(
            Xh, Xl, Bqh, Bql, bqkv, nullptr, qkvh, qkvl, MM, NQKV, DD);
    }

    // 2) Flash attention (QK 2x, PV 1x — R12 config)
    {
        dim3 grid(SS / 128, BB * HH);
        flash_h16_kernel<<<grid, 256, flash_smem>>>(qkvh, qkvl, attnh, attnl);
    }

    // 3) out = attn @ Wout + bout  (1x fp16: attnh.Wh only)
    {
        dim3 grid(DD / 128, MM / 128);
        gemm_h16_kernel<false, 1><<<grid, 256, gemm_smem>>>(
            attnh, attnl, Boh, Bol, bout, out, nullptr, nullptr, MM, DD, DD);
    }
}